// round 15
// baseline (speedup 1.0000x reference)
#include <cuda_runtime.h>
#include <cuda_fp16.h>
#include <cstdint>
#include <math.h>

#define NN    20000
#define EE    320000
#define ET    (EE + NN)
#define FIN   128
#define HID   128
#define HEADS 4
#define DBIG  (HEADS * HID)
#define BGR   64
#define SLOPE 0.2f
#define RTC   157              // (NN + 127) / 128 row tiles

// ----------------------------------------------------------------------------
// Scratch (device globals)
// ----------------------------------------------------------------------------
__device__ __half g_xlr[(size_t)NN * 1024];  // fused [xl | xr] GEMM output (fp16)
__device__ __half g_h1[(size_t)NN * DBIG];   // pair-permuted fp16 (GEMM input)
__device__ __half g_h2[(size_t)NN * DBIG];   // pair-permuted fp16 (GEMM input)
__device__ float  g_h3[(size_t)NN * HID];    // natural fp32
__device__ __half g_xp[(size_t)NN * FIN];    // x, pair-permuted fp16
__device__ __half g_wt1[1024 * 128];         // layer-1 weights^T (l|r)
__device__ __half g_wt2[1024 * 512];         // layer-2 weights^T (l|r)
__device__ __half g_wt3[256 * 512];          // layer-3 weights^T (l|r)
__device__ int    g_deg[NN];
__device__ int    g_off[NN + 1];
__device__ int    g_cursor[NN];
__device__ int    g_csr_src[ET];
__device__ float  g_pool[BGR * HID];

// ----------------------------------------------------------------------------
// Helpers
// ----------------------------------------------------------------------------
__device__ __forceinline__ int pairperm(int p) { return ((p & 3) << 2) | (p >> 2); }
__device__ __forceinline__ int kpos(int k) {
    return (k & ~31) | (pairperm((k >> 1) & 15) << 1) | (k & 1);
}
__device__ __forceinline__ uint32_t smem_u32(const void* p) {
    uint32_t a;
    asm("{ .reg .u64 t; cvta.to.shared.u64 t, %1; cvt.u32.u64 %0, t; }" : "=r"(a) : "l"(p));
    return a;
}
__device__ __forceinline__ void cp_async16(uint32_t dst, const void* src) {
    asm volatile("cp.async.cg.shared.global [%0], [%1], 16;" :: "r"(dst), "l"(src) : "memory");
}
__device__ __forceinline__ void cp_commit() {
    asm volatile("cp.async.commit_group;" ::: "memory");
}
template <int N>
__device__ __forceinline__ void cp_wait() {
    asm volatile("cp.async.wait_group %0;" :: "n"(N) : "memory");
}
__device__ __forceinline__ float4 ldh4(const __half* p) {
    uint2 u = *(const uint2*)p;
    __half2 h0 = *(__half2*)&u.x, h1 = *(__half2*)&u.y;
    float2 f0 = __half22float2(h0), f1 = __half22float2(h1);
    return make_float4(f0.x, f0.y, f1.x, f1.y);
}
__device__ __forceinline__ float4 cvt4(uint32_t a, uint32_t b) {
    float2 f0 = __half22float2(*(__half2*)&a), f1 = __half22float2(*(__half2*)&b);
    return make_float4(f0.x, f0.y, f1.x, f1.y);
}

// ----------------------------------------------------------------------------
// L1: permute_x (blocks < 10000) + zero g_deg (blocks >= 10000)
// ----------------------------------------------------------------------------
__global__ void permute_zero_kernel(const float* __restrict__ x, __half* __restrict__ xp) {
    int b = blockIdx.x, tid = threadIdx.x;
    if (b < 10000) {
        int idx = b * 256 + tid;
        int row = idx >> 7, k = idx & 127;
        xp[(size_t)row * FIN + kpos(k)] = __float2half_rn(x[idx]);
    } else {
        int i = (b - 10000) * 256 + tid;
        if (i < NN) g_deg[i] = 0;
    }
}

// ----------------------------------------------------------------------------
// transpose tile worker: WT[m][kpos(k)] = fp16(W[k][m]) for one 32x32 tile
// ----------------------------------------------------------------------------
__device__ __forceinline__ void do_transpose(const float* __restrict__ W,
                                             __half* __restrict__ WT,
                                             int K, int M, int bx, int by, int tid) {
    __shared__ float t[32][33];
    int m0 = bx * 32, k0 = by * 32;
    int tx = tid & 31, ty = tid >> 5;
#pragma unroll
    for (int i = 0; i < 32; i += 8)
        t[ty + i][tx] = W[(size_t)(k0 + ty + i) * M + m0 + tx];
    __syncthreads();
    int kp = k0 + kpos(tx);
#pragma unroll
    for (int i = 0; i < 32; i += 8)
        WT[(size_t)(m0 + ty + i) * K + kp] = __float2half_rn(t[tx][ty + i]);
}

// ----------------------------------------------------------------------------
// L2: prep = transposes + hist. Branch is block-uniform.
// ----------------------------------------------------------------------------
__global__ void prep_kernel(const float* __restrict__ Wl1, const float* __restrict__ Wr1,
                            const float* __restrict__ Wl2, const float* __restrict__ Wr2,
                            const float* __restrict__ Wl3, const float* __restrict__ Wr3,
                            const int* __restrict__ edst) {
    int b = blockIdx.x, tid = threadIdx.x;
    if (b < 128) {
        int bz = b >> 6, i = b & 63;
        int bx = i & 15, by = i >> 4;
        do_transpose(bz ? Wr1 : Wl1, g_wt1 + (size_t)bz * 512 * 128, 128, 512, bx, by, tid);
    } else if (b < 640) {
        int i = b - 128;
        int bz = i >> 8; i &= 255;
        int bx = i & 15, by = i >> 4;
        do_transpose(bz ? Wr2 : Wl2, g_wt2 + (size_t)bz * 512 * 512, 512, 512, bx, by, tid);
    } else if (b < 768) {
        int i = b - 640;
        int bz = i >> 6; i &= 63;
        int bx = i & 3, by = i >> 2;
        do_transpose(bz ? Wr3 : Wl3, g_wt3 + (size_t)bz * 128 * 512, 512, 128, bx, by, tid);
    } else {
        int e = (b - 768) * 256 + tid;
        if (e >= ET) return;
        int d = (e < EE) ? edst[e] : (e - EE);
        atomicAdd(&g_deg[d], 1);
    }
}

// ----------------------------------------------------------------------------
// scan (one 256-thread block)
// ----------------------------------------------------------------------------
__device__ void scan_256() {
    __shared__ int part[256];
    int t = threadIdx.x;
    const int chunk = (NN + 255) / 256;
    int beg = t * chunk, end = beg + chunk;
    if (end > NN) end = NN;
    int s = 0;
    for (int i = beg; i < end; i++) s += g_deg[i];
    part[t] = s;
    __syncthreads();
    for (int o = 1; o < 256; o <<= 1) {
        int v = (t >= o) ? part[t - o] : 0;
        __syncthreads();
        part[t] += v;
        __syncthreads();
    }
    int run = (t == 0) ? 0 : part[t - 1];
    for (int i = beg; i < end; i++) {
        g_off[i] = run; g_cursor[i] = run; run += g_deg[i];
    }
    if (t == 255) g_off[NN] = part[255];
}

__global__ void scatter_kernel(const int* __restrict__ esrc, const int* __restrict__ edst) {
    int e = blockIdx.x * blockDim.x + threadIdx.x;
    if (e >= ET) return;
    int s, d;
    if (e < EE) { s = esrc[e]; d = edst[e]; }
    else        { s = e - EE;  d = e - EE; }
    int pos = atomicAdd(&g_cursor[d], 1);
    g_csr_src[pos] = s;
}

// ----------------------------------------------------------------------------
// fp16 mma.sync m16n8k16 GEMM body: 4-stage cp.async, block 128x128,
// warp 64x32, 8 warps, fp16 output.
// ----------------------------------------------------------------------------
#define STAGES 4
#define SMEM_A_TILE (128 * 32)
#define SMEM_B_TILE (128 * 32)
#define SMEM_STAGE  (SMEM_A_TILE + SMEM_B_TILE)

__device__ __forceinline__ void gemm_body(
    __half* smh, const __half* __restrict__ A, const __half* __restrict__ BT,
    const float* __restrict__ bias_l, const float* __restrict__ bias_r,
    __half* __restrict__ C, int Nrows, int K, int Mout, int Mhalf,
    int bxi, int byi) {
    uint32_t uS = smem_u32(smh);

    int tid = threadIdx.x;
    int lane = tid & 31, wid = tid >> 5;
    int wm = wid & 1;
    int wn = wid >> 1;
    int g = lane >> 2, t = lane & 3;
    int brow = bxi * 128;
    int bcol = byi * 128;

    int cprow = tid >> 2;
    int cc = tid & 3;

    float acc[4][4][4];
#pragma unroll
    for (int a = 0; a < 4; a++)
#pragma unroll
        for (int b = 0; b < 4; b++)
#pragma unroll
            for (int c = 0; c < 4; c++) acc[a][b][c] = 0.f;

    const int NT = K >> 5;

    auto load_tile = [&](int kt, int buf) {
        int k0 = kt << 5;
        uint32_t base = uS + (uint32_t)(buf * SMEM_STAGE) * 2;
#pragma unroll
        for (int i = 0; i < 2; i++) {
            int row = cprow + i * 64;
            int gr = brow + row; if (gr >= Nrows) gr = Nrows - 1;
            cp_async16(base + (uint32_t)(row * 32 + cc * 8) * 2,
                       A + (size_t)gr * K + k0 + cc * 8);
        }
        base += (uint32_t)SMEM_A_TILE * 2;
#pragma unroll
        for (int i = 0; i < 2; i++) {
            int row = cprow + i * 64;
            cp_async16(base + (uint32_t)(row * 32 + cc * 8) * 2,
                       BT + (size_t)(bcol + row) * K + k0 + cc * 8);
        }
    };

#pragma unroll
    for (int p = 0; p < STAGES - 1; p++) {
        if (p < NT) load_tile(p, p);
        cp_commit();
    }

    for (int kt = 0; kt < NT; kt++) {
        cp_wait<STAGES - 2>();
        __syncthreads();
        int nk = kt + STAGES - 1;
        if (nk < NT) load_tile(nk, nk & (STAGES - 1));
        cp_commit();

        const __half* Ab = smh + (kt & (STAGES - 1)) * SMEM_STAGE;
        const __half* Bb = Ab + SMEM_A_TILE;

        uint4 bfv[4];
#pragma unroll
        for (int nt = 0; nt < 4; nt++) {
            int n = wn * 32 + nt * 8 + g;
            bfv[nt] = *(const uint4*)(Bb + n * 32 + t * 8);
        }
#pragma unroll
        for (int mt = 0; mt < 4; mt++) {
            int r = wm * 64 + mt * 16 + g;
            uint4 lo = *(const uint4*)(Ab + r * 32 + t * 8);
            uint4 hi = *(const uint4*)(Ab + (r + 8) * 32 + t * 8);
#pragma unroll
            for (int nt = 0; nt < 4; nt++) {
                asm volatile(
                    "mma.sync.aligned.m16n8k16.row.col.f32.f16.f16.f32 "
                    "{%0,%1,%2,%3}, {%4,%5,%6,%7}, {%8,%9}, {%0,%1,%2,%3};"
                    : "+f"(acc[mt][nt][0]), "+f"(acc[mt][nt][1]),
                      "+f"(acc[mt][nt][2]), "+f"(acc[mt][nt][3])
                    : "r"(lo.x), "r"(hi.x), "r"(lo.y), "r"(hi.y),
                      "r"(bfv[nt].x), "r"(bfv[nt].y));
                asm volatile(
                    "mma.sync.aligned.m16n8k16.row.col.f32.f16.f16.f32 "
                    "{%0,%1,%2,%3}, {%4,%5,%6,%7}, {%8,%9}, {%0,%1,%2,%3};"
                    : "+f"(acc[mt][nt][0]), "+f"(acc[mt][nt][1]),
                      "+f"(acc[mt][nt][2]), "+f"(acc[mt][nt][3])
                    : "r"(lo.z), "r"(hi.z), "r"(lo.w), "r"(hi.w),
                      "r"(bfv[nt].z), "r"(bfv[nt].w));
            }
        }
    }

#pragma unroll
    for (int mt = 0; mt < 4; mt++) {
        int r0 = brow + wm * 64 + mt * 16 + g;
#pragma unroll
        for (int nt = 0; nt < 4; nt++) {
            int c = bcol + wn * 32 + nt * 8 + 2 * t;
            float b0, b1;
            if (c < Mhalf) { b0 = bias_l[c]; b1 = bias_l[c + 1]; }
            else           { b0 = bias_r[c - Mhalf]; b1 = bias_r[c - Mhalf + 1]; }
            if (r0 < Nrows) {
                *(__half2*)(C + (size_t)r0 * Mout + c) =
                    __floats2half2_rn(acc[mt][nt][0] + b0, acc[mt][nt][1] + b1);
            }
            if (r0 + 8 < Nrows) {
                *(__half2*)(C + (size_t)(r0 + 8) * Mout + c) =
                    __floats2half2_rn(acc[mt][nt][2] + b0, acc[mt][nt][3] + b1);
            }
        }
    }
}

__global__ __launch_bounds__(256, 2)
void gemm_mma(const __half* __restrict__ A, const __half* __restrict__ BT,
              const float* __restrict__ bias_l, const float* __restrict__ bias_r,
              __half* __restrict__ C, int Nrows, int K, int Mout, int Mhalf) {
    extern __shared__ __half smh[];
    gemm_body(smh, A, BT, bias_l, bias_r, C, Nrows, K, Mout, Mhalf,
              blockIdx.x, blockIdx.y);
}

__global__ __launch_bounds__(256, 2)
void gemm1_scan(const __half* __restrict__ A, const __half* __restrict__ BT,
                const float* __restrict__ bias_l, const float* __restrict__ bias_r,
                __half* __restrict__ C) {
    extern __shared__ __half smh[];
    int b = blockIdx.x;
    if (b == RTC * 8) { scan_256(); return; }
    gemm_body(smh, A, BT, bias_l, bias_r, C, NN, 128, 1024, 512,
              b % RTC, b / RTC);
}

// ----------------------------------------------------------------------------
// Merged-head GATv2 attention (H=4): ONE warp per node. Lane owns 16 channels
// (head = lane>>3). One 3-deep intra-group shfl tree per edge reduces all 4
// heads simultaneously. Output pair-permuted fp16.
// ----------------------------------------------------------------------------
__global__ __launch_bounds__(256)
void gatv2_h4m(const __half* __restrict__ xlr,
               const float* __restrict__ att, const float* __restrict__ bias,
               __half* __restrict__ out) {
    const int S = 1024, D = 512;
    int node = blockIdx.x * 8 + (threadIdx.x >> 5);
    if (node >= NN) return;
    int lane = threadIdx.x & 31;
    int head = lane >> 3;
    int ch0 = head * 128 + (lane & 7) * 16;

    const __half* prv = xlr + (size_t)node * S + D + ch0;
    float4 rv0 = ldh4(prv), rv1 = ldh4(prv + 4), rv2 = ldh4(prv + 8), rv3 = ldh4(prv + 12);
    float4 av0 = *(const float4*)(att + ch0);
    float4 av1 = *(const float4*)(att + ch0 + 4);
    float4 av2 = *(const float4*)(att + ch0 + 8);
    float4 av3 = *(const float4*)(att + ch0 + 12);
    float4 ac0 = make_float4(0.f, 0.f, 0.f, 0.f), ac1 = ac0, ac2 = ac0, ac3 = ac0;

    int s = g_off[node], e = g_off[node + 1];
    float m = -1e30f, den = 0.f;

    for (int j = s; j < e; j++) {
        int src = g_csr_src[j];
        const __half* px = xlr + (size_t)src * S + ch0;
        uint4 u0 = *(const uint4*)px;
        uint4 u1 = *(const uint4*)(px + 8);
        float4 x0 = cvt4(u0.x, u0.y), x1 = cvt4(u0.z, u0.w);
        float4 x2 = cvt4(u1.x, u1.y), x3 = cvt4(u1.z, u1.w);

        float p = 0.f, tt;
        tt = x0.x + rv0.x; tt = tt > 0.f ? tt : SLOPE * tt; p += av0.x * tt;
        tt = x0.y + rv0.y; tt = tt > 0.f ? tt : SLOPE * tt; p += av0.y * tt;
        tt = x0.z + rv0.z; tt = tt > 0.f ? tt : SLOPE * tt; p += av0.z * tt;
        tt = x0.w + rv0.w; tt = tt > 0.f ? tt : SLOPE * tt; p += av0.w * tt;
        tt = x1.x + rv1.x; tt = tt > 0.f ? tt : SLOPE * tt; p += av1.x * tt;
        tt = x1.y + rv1.y; tt = tt > 0.f ? tt : SLOPE * tt; p += av1.y * tt;
        tt = x1.z + rv1.z; tt = tt > 0.f ? tt : SLOPE * tt; p += av1.z * tt;
        tt = x1.w + rv1.w; tt = tt > 0.f ? tt : SLOPE * tt; p += av1.w * tt;
        tt = x2.x + rv2.x; tt = tt > 0.f ? tt : SLOPE * tt; p += av2.x * tt;
        tt = x2.y + rv2.y; tt = tt > 0.f ? tt : SLOPE * tt; p += av2.y * tt;
        tt = x2.z + rv2.z; tt = tt > 0.f ? tt : SLOPE * tt; p += av2.z * tt;
        tt = x2.w + rv2.w; tt = tt > 0.f ? tt : SLOPE * tt; p += av2.w * tt;
        tt = x3.x + rv3.x; tt = tt > 0.f ? tt : SLOPE * tt; p += av3.x * tt;
        tt = x3.y + rv3.y; tt = tt > 0.f ? tt : SLOPE * tt; p += av3.y * tt;
        tt = x3.z + rv3.z; tt = tt > 0.f ? tt : SLOPE * tt; p += av3.z * tt;
        tt = x3.w + rv3.w; tt = tt > 0.f ? tt : SLOPE * tt; p += av3.w * tt;
        // reduce within 8-lane head group
        p += __shfl_xor_sync(0xffffffffu, p, 4);
        p += __shfl_xor_sync(0xffffffffu, p, 2);
        p += __shfl_xor_sync(0xffffffffu, p, 1);

        if (__any_sync(0xffffffffu, p > m)) {
            float mm = fmaxf(m, p);
            float sc = __expf(m - mm);   // 1.0 for groups that didn't update
            m = mm;
            den *= sc;
            ac0.x *= sc; ac0.y *= sc; ac0.z *= sc; ac0.w *= sc;
            ac1.x *= sc; ac1.y *= sc; ac1.z *= sc; ac1.w *= sc;
            ac2.x *= sc; ac2.y *= sc; ac2.z *= sc; ac2.w *= sc;
            ac3.x *= sc; ac3.y *= sc; ac3.z *= sc; ac3.w *= sc;
        }
        float w = __expf(p - m);
        den += w;
        ac0.x += w * x0.x; ac0.y += w * x0.y; ac0.z += w * x0.z; ac0.w += w * x0.w;
        ac1.x += w * x1.x; ac1.y += w * x1.y; ac1.z += w * x1.z; ac1.w += w * x1.w;
        ac2.x += w * x2.x; ac2.y += w * x2.y; ac2.z += w * x2.z; ac2.w += w * x2.w;
        ac3.x += w * x3.x; ac3.y += w * x3.y; ac3.z += w * x3.z; ac3.w += w * x3.w;
    }

    float inv = 1.f / den;
    float o[16];
    float4 b0 = *(const float4*)(bias + ch0);
    float4 b1 = *(const float4*)(bias + ch0 + 4);
    float4 b2 = *(const float4*)(bias + ch0 + 8);
    float4 b3 = *(const float4*)(bias + ch0 + 12);
    float v;
    v = ac0.x * inv + b0.x; o[0]  = v > 0.f ? v : expm1f(v);
    v = ac0.y * inv + b0.y; o[1]  = v > 0.f ? v : expm1f(v);
    v = ac0.z * inv + b0.z; o[2]  = v > 0.f ? v : expm1f(v);
    v = ac0.w * inv + b0.w; o[3]  = v > 0.f ? v : expm1f(v);
    v = ac1.x * inv + b1.x; o[4]  = v > 0.f ? v : expm1f(v);
    v = ac1.y * inv + b1.y; o[5]  = v > 0.f ? v : expm1f(v);
    v = ac1.z * inv + b1.z; o[6]  = v > 0.f ? v : expm1f(v);
    v = ac1.w * inv + b1.w; o[7]  = v > 0.f ? v : expm1f(v);
    v = ac2.x * inv + b2.x; o[8]  = v > 0.f ? v : expm1f(v);
    v = ac2.y * inv + b2.y; o[9]  = v > 0.f ? v : expm1f(v);
    v = ac2.z * inv + b2.z; o[10] = v > 0.f ? v : expm1f(v);
    v = ac2.w * inv + b2.w; o[11] = v > 0.f ? v : expm1f(v);
    v = ac3.x * inv + b3.x; o[12] = v > 0.f ? v : expm1f(v);
    v = ac3.y * inv + b3.y; o[13] = v > 0.f ? v : expm1f(v);
    v = ac3.z * inv + b3.z; o[14] = v > 0.f ? v : expm1f(v);
    v = ac3.w * inv + b3.w; o[15] = v > 0.f ? v : expm1f(v);

    // pair-permuted store: lane's pairs j=0..7, in-group pair idx = 8*(lane&1)+j
    int a32 = (lane & 7) >> 1;
    size_t base = (size_t)node * D + head * 128 + a32 * 32;
    int pb = 8 * (lane & 1);
#pragma unroll
    for (int j = 0; j < 8; j++) {
        int q = pairperm(pb + j);
        *(__half2*)(out + base + 2 * q) = __floats2half2_rn(o[2 * j], o[2 * j + 1]);
    }
}

// ----------------------------------------------------------------------------
// GATv2 attention H=1 (layer 3): unchanged 4-edge ILP, one warp per node.
// ----------------------------------------------------------------------------
__global__ __launch_bounds__(256)
void gatv2_h1(const __half* __restrict__ xlr,
              const float* __restrict__ att, const float* __restrict__ bias,
              float* __restrict__ out) {
    const int S = 256, D = 128;
    int node = blockIdx.x * 8 + (threadIdx.x >> 5);
    if (node >= NN) return;
    int lane = threadIdx.x & 31;
    int cbase = lane * 4;

    float4 rv = ldh4(xlr + (size_t)node * S + D + cbase);
    float4 av = *(const float4*)(att + cbase);
    int s = g_off[node], e = g_off[node + 1];

    float m = -1e30f, den = 0.f;
    float4 acc = make_float4(0.f, 0.f, 0.f, 0.f);

    int j = s;
    for (; j + 4 <= e; j += 4) {
        int s0 = g_csr_src[j],     s1 = g_csr_src[j + 1];
        int s2 = g_csr_src[j + 2], s3 = g_csr_src[j + 3];
        float4 x0 = ldh4(xlr + (size_t)s0 * S + cbase);
        float4 x1 = ldh4(xlr + (size_t)s1 * S + cbase);
        float4 x2 = ldh4(xlr + (size_t)s2 * S + cbase);
        float4 x3 = ldh4(xlr + (size_t)s3 * S + cbase);
        float p0 = 0.f, p1 = 0.f, p2 = 0.f, p3 = 0.f, tt;
        tt = x0.x + rv.x; tt = tt > 0.f ? tt : SLOPE * tt; p0 += av.x * tt;
        tt = x1.x + rv.x; tt = tt > 0.f ? tt : SLOPE * tt; p1 += av.x * tt;
        tt = x2.x + rv.x; tt = tt > 0.f ? tt : SLOPE * tt; p2 += av.x * tt;
        tt = x3.x + rv.x; tt = tt > 0.f ? tt : SLOPE * tt; p3 += av.x * tt;
        tt = x0.y + rv.y; tt = tt > 0.f ? tt : SLOPE * tt; p0 += av.y * tt;
        tt = x1.y + rv.y; tt = tt > 0.f ? tt : SLOPE * tt; p1 += av.y * tt;
        tt = x2.y + rv.y; tt = tt > 0.f ? tt : SLOPE * tt; p2 += av.y * tt;
        tt = x3.y + rv.y; tt = tt > 0.f ? tt : SLOPE * tt; p3 += av.y * tt;
        tt = x0.z + rv.z; tt = tt > 0.f ? tt : SLOPE * tt; p0 += av.z * tt;
        tt = x1.z + rv.z; tt = tt > 0.f ? tt : SLOPE * tt; p1 += av.z * tt;
        tt = x2.z + rv.z; tt = tt > 0.f ? tt : SLOPE * tt; p2 += av.z * tt;
        tt = x3.z + rv.z; tt = tt > 0.f ? tt : SLOPE * tt; p3 += av.z * tt;
        tt = x0.w + rv.w; tt = tt > 0.f ? tt : SLOPE * tt; p0 += av.w * tt;
        tt = x1.w + rv.w; tt = tt > 0.f ? tt : SLOPE * tt; p1 += av.w * tt;
        tt = x2.w + rv.w; tt = tt > 0.f ? tt : SLOPE * tt; p2 += av.w * tt;
        tt = x3.w + rv.w; tt = tt > 0.f ? tt : SLOPE * tt; p3 += av.w * tt;
#pragma unroll
        for (int o = 16; o; o >>= 1) {
            p0 += __shfl_xor_sync(0xffffffffu, p0, o);
            p1 += __shfl_xor_sync(0xffffffffu, p1, o);
            p2 += __shfl_xor_sync(0xffffffffu, p2, o);
            p3 += __shfl_xor_sync(0xffffffffu, p3, o);
        }
        float mm = fmaxf(fmaxf(m, fmaxf(p0, p1)), fmaxf(p2, p3));
        if (mm > m) {
            float sc = __expf(m - mm);
            m = mm;
            den *= sc; acc.x *= sc; acc.y *= sc; acc.z *= sc; acc.w *= sc;
        }
        float w0 = __expf(p0 - m), w1 = __expf(p1 - m);
        float w2 = __expf(p2 - m), w3 = __expf(p3 - m);
        den += (w0 + w1) + (w2 + w3);
        acc.x += w0 * x0.x + w1 * x1.x + w2 * x2.x + w3 * x3.x;
        acc.y += w0 * x0.y + w1 * x1.y + w2 * x2.y + w3 * x3.y;
        acc.z += w0 * x0.z + w1 * x1.z + w2 * x2.z + w3 * x3.z;
        acc.w += w0 * x0.w + w1 * x1.w + w2 * x2.w + w3 * x3.w;
    }
    for (; j < e; j++) {
        int s0 = g_csr_src[j];
        float4 x0 = ldh4(xlr + (size_t)s0 * S + cbase);
        float tt, p0 = 0.f;
        tt = x0.x + rv.x; tt = tt > 0.f ? tt : SLOPE * tt; p0 += av.x * tt;
        tt = x0.y + rv.y; tt = tt > 0.f ? tt : SLOPE * tt; p0 += av.y * tt;
        tt = x0.z + rv.z; tt = tt > 0.f ? tt : SLOPE * tt; p0 += av.z * tt;
        tt = x0.w + rv.w; tt = tt > 0.f ? tt : SLOPE * tt; p0 += av.w * tt;
#pragma unroll
        for (int o = 16; o; o >>= 1) p0 += __shfl_xor_sync(0xffffffffu, p0, o);
        if (p0 > m) {
            float sc = __expf(m - p0);
            m = p0;
            den *= sc; acc.x *= sc; acc.y *= sc; acc.z *= sc; acc.w *= sc;
        }
        float w0 = __expf(p0 - m);
        den += w0;
        acc.x += w0 * x0.x; acc.y += w0 * x0.y; acc.z += w0 * x0.z; acc.w += w0 * x0.w;
    }

    float inv = 1.f / den;
    float4 o4;
    float v;
    v = acc.x * inv + bias[cbase + 0]; o4.x = v > 0.f ? v : expm1f(v);
    v = acc.y * inv + bias[cbase + 1]; o4.y = v > 0.f ? v : expm1f(v);
    v = acc.z * inv + bias[cbase + 2]; o4.z = v > 0.f ? v : expm1f(v);
    v = acc.w * inv + bias[cbase + 3]; o4.w = v > 0.f ? v : expm1f(v);
    *(float4*)(out + (size_t)node * D + cbase) = o4;
}

// ----------------------------------------------------------------------------
// Pooling (batch sorted -> contiguous segments) + MLP
// ----------------------------------------------------------------------------
__global__ void pool_kernel(const int* __restrict__ batch) {
    int g = blockIdx.x;
    int t = threadIdx.x;
    __shared__ int seg[2];
    if (t < 2) {
        int target = g + t;
        int lo = 0, hi = NN;
        while (lo < hi) {
            int mid = (lo + hi) >> 1;
            if (batch[mid] < target) lo = mid + 1; else hi = mid;
        }
        seg[t] = lo;
    }
    __syncthreads();
    int lo = seg[0], hi = seg[1];
    float sum = 0.f;
    for (int i = lo; i < hi; i++) sum += g_h3[(size_t)i * HID + t];
    float c = fmaxf((float)(hi - lo), 1.0f);
    g_pool[g * HID + t] = sum / c;
}
__global__ void mlp_kernel(const float* __restrict__ W1, const float* __restrict__ b1,
                           const float* __restrict__ W2, const float* __restrict__ b2,
                           float* __restrict__ out) {
    int g = blockIdx.x;
    int t = threadIdx.x;
    __shared__ float p[HID];
    __shared__ float hid[HID];
    __shared__ float red[HID];
    p[t] = g_pool[g * HID + t];
    __syncthreads();
    float a = 0.f;
    for (int k = 0; k < HID; k++) a += p[k] * W1[k * HID + t];
    hid[t] = fmaxf(a + b1[t], 0.f);
    __syncthreads();
    for (int o = 0; o < 2; o++) {
        red[t] = hid[t] * W2[t * 2 + o];
        __syncthreads();
        for (int stp = 64; stp; stp >>= 1) {
            if (t < stp) red[t] += red[t + stp];
            __syncthreads();
        }
        if (t == 0) out[g * 2 + o] = red[0] + b2[o];
        __syncthreads();
    }
}

// ----------------------------------------------------------------------------
// Launch
// ----------------------------------------------------------------------------
extern "C" void kernel_launch(void* const* d_in, const int* in_sizes, int n_in,
                              void* d_out, int out_size) {
    const float* x     = (const float*)d_in[0];
    const int*   esrc  = (const int*)d_in[1];
    const int*   edst  = (const int*)d_in[2];
    const int*   batch = (const int*)d_in[3];
    const float* Wl1 = (const float*)d_in[4];
    const float* Wr1 = (const float*)d_in[5];
    const float* bl1 = (const float*)d_in[6];
    const float* br1 = (const float*)d_in[7];
    const float* att1  = (const float*)d_in[8];
    const float* bias1 = (const float*)d_in[9];
    const float* Wl2 = (const float*)d_in[10];
    const float* Wr2 = (const float*)d_in[11];
    const float* bl2 = (const float*)d_in[12];
    const float* br2 = (const float*)d_in[13];
    const float* att2  = (const float*)d_in[14];
    const float* bias2 = (const float*)d_in[15];
    const float* Wl3 = (const float*)d_in[16];
    const float* Wr3 = (const float*)d_in[17];
    const float* bl3 = (const float*)d_in[18];
    const float* br3 = (const float*)d_in[19];
    const float* att3  = (const float*)d_in[20];
    const float* bias3 = (const float*)d_in[21];
    const float* Wm1 = (const float*)d_in[22];
    const float* bm1 = (const float*)d_in[23];
    const float* Wm2 = (const float*)d_in[24];
    const float* bm2 = (const float*)d_in[25];
    float* out = (float*)d_out;

    float *p_h3;
    __half *p_xlr, *p_h1, *p_h2, *p_xp, *p_wt1, *p_wt2, *p_wt3;
    cudaGetSymbolAddress((void**)&p_xlr, g_xlr);
    cudaGetSymbolAddress((void**)&p_h1, g_h1);
    cudaGetSymbolAddress((void**)&p_h2, g_h2);
    cudaGetSymbolAddress((void**)&p_h3, g_h3);
    cudaGetSymbolAddress((void**)&p_xp, g_xp);
    cudaGetSymbolAddress((void**)&p_wt1, g_wt1);
    cudaGetSymbolAddress((void**)&p_wt2, g_wt2);
    cudaGetSymbolAddress((void**)&p_wt3, g_wt3);

    const int SMEM = STAGES * SMEM_STAGE * 2;  // 65536 bytes
    cudaFuncSetAttribute(gemm_mma, cudaFuncAttributeMaxDynamicSharedMemorySize, SMEM);
    cudaFuncSetAttribute(gemm1_scan, cudaFuncAttributeMaxDynamicSharedMemorySize, SMEM);

    const int HIST_BLOCKS = (ET + 255) / 256;  // 1329
    const int AB = (NN + 7) / 8;               // 2500 attention blocks

    permute_zero_kernel<<<10000 + (NN + 255) / 256, 256>>>(x, p_xp);
    prep_kernel<<<768 + HIST_BLOCKS, 256>>>(Wl1, Wr1, Wl2, Wr2, Wl3, Wr3, edst);
    gemm1_scan<<<RTC * 8 + 1, 256, SMEM>>>(p_xp, p_wt1, bl1, br1, p_xlr);
    scatter_kernel<<<HIST_BLOCKS, 256>>>(esrc, edst);
    gatv2_h4m<<<AB, 256>>>(p_xlr, att1, bias1, p_h1);
    gemm_mma<<<dim3(RTC, 8), 256, SMEM>>>(p_h1, p_wt2, bl2, br2, p_xlr, NN, 512, 1024, 512);
    gatv2_h4m<<<AB, 256>>>(p_xlr, att2, bias2, p_h2);
    gemm_mma<<<dim3(RTC, 2), 256, SMEM>>>(p_h2, p_wt3, bl3, br3, p_xlr, NN, 512, 256, 128);
    gatv2_h1<<<AB, 256>>>(p_xlr, att3, bias3, p_h3);
    pool_kernel<<<BGR, HID>>>(batch);
    mlp_kernel<<<BGR, HID>>>(Wm1, bm1, Wm2, bm2, out);
}

// round 16
// speedup vs baseline: 1.0365x; 1.0365x over previous
#include <cuda_runtime.h>
#include <cuda_fp16.h>
#include <cstdint>
#include <math.h>

#define NN    20000
#define EE    320000
#define ET    (EE + NN)
#define FIN   128
#define HID   128
#define HEADS 4
#define DBIG  (HEADS * HID)
#define BGR   64
#define SLOPE 0.2f
#define RTC   157              // (NN + 127) / 128 row tiles
#define HIST_BLOCKS ((ET + 255) / 256)   // 1329

// ----------------------------------------------------------------------------
// Scratch (device globals)
// ----------------------------------------------------------------------------
__device__ __half g_xlr[(size_t)NN * 1024];
__device__ __half g_h1[(size_t)NN * DBIG];
__device__ __half g_h2[(size_t)NN * DBIG];
__device__ float  g_h3[(size_t)NN * HID];
__device__ __half g_xp[(size_t)NN * FIN];
__device__ __half g_wt1[1024 * 128];
__device__ __half g_wt2[1024 * 512];
__device__ __half g_wt3[256 * 512];
__device__ int    g_deg[NN];
__device__ int    g_off[NN + 1];
__device__ int    g_cursor[NN];
__device__ int    g_csr_src[ET];
__device__ unsigned int g_done;

// ----------------------------------------------------------------------------
// Helpers
// ----------------------------------------------------------------------------
__device__ __forceinline__ int pairperm(int p) { return ((p & 3) << 2) | (p >> 2); }
__device__ __forceinline__ int kpos(int k) {
    return (k & ~31) | (pairperm((k >> 1) & 15) << 1) | (k & 1);
}
__device__ __forceinline__ uint32_t smem_u32(const void* p) {
    uint32_t a;
    asm("{ .reg .u64 t; cvta.to.shared.u64 t, %1; cvt.u32.u64 %0, t; }" : "=r"(a) : "l"(p));
    return a;
}
__device__ __forceinline__ void cp_async16(uint32_t dst, const void* src) {
    asm volatile("cp.async.cg.shared.global [%0], [%1], 16;" :: "r"(dst), "l"(src) : "memory");
}
__device__ __forceinline__ void cp_commit() {
    asm volatile("cp.async.commit_group;" ::: "memory");
}
template <int N>
__device__ __forceinline__ void cp_wait() {
    asm volatile("cp.async.wait_group %0;" :: "n"(N) : "memory");
}
__device__ __forceinline__ float4 ldh4(const __half* p) {
    uint2 u = *(const uint2*)p;
    __half2 h0 = *(__half2*)&u.x, h1 = *(__half2*)&u.y;
    float2 f0 = __half22float2(h0), f1 = __half22float2(h1);
    return make_float4(f0.x, f0.y, f1.x, f1.y);
}

// ----------------------------------------------------------------------------
// L1: permute_x + zero deg + zero done counter
// ----------------------------------------------------------------------------
__global__ void permute_zero_kernel(const float* __restrict__ x, __half* __restrict__ xp) {
    int b = blockIdx.x, tid = threadIdx.x;
    if (b == 0 && tid == 0) g_done = 0;
    if (b < 10000) {
        int idx = b * 256 + tid;
        int row = idx >> 7, k = idx & 127;
        xp[(size_t)row * FIN + kpos(k)] = __float2half_rn(x[idx]);
    } else {
        int i = (b - 10000) * 256 + tid;
        if (i < NN) g_deg[i] = 0;
    }
}

// ----------------------------------------------------------------------------
// transpose tile worker
// ----------------------------------------------------------------------------
__device__ __forceinline__ void do_transpose(const float* __restrict__ W,
                                             __half* __restrict__ WT,
                                             int K, int M, int bx, int by, int tid) {
    __shared__ float t[32][33];
    int m0 = bx * 32, k0 = by * 32;
    int tx = tid & 31, ty = tid >> 5;
#pragma unroll
    for (int i = 0; i < 32; i += 8)
        t[ty + i][tx] = W[(size_t)(k0 + ty + i) * M + m0 + tx];
    __syncthreads();
    int kp = k0 + kpos(tx);
#pragma unroll
    for (int i = 0; i < 32; i += 8)
        WT[(size_t)(m0 + ty + i) * K + kp] = __float2half_rn(t[tx][ty + i]);
}

// ----------------------------------------------------------------------------
// scan (one 256-thread block)
// ----------------------------------------------------------------------------
__device__ void scan_256() {
    __shared__ int part[256];
    int t = threadIdx.x;
    const int chunk = (NN + 255) / 256;
    int beg = t * chunk, end = beg + chunk;
    if (end > NN) end = NN;
    int s = 0;
    for (int i = beg; i < end; i++) s += g_deg[i];
    part[t] = s;
    __syncthreads();
    for (int o = 1; o < 256; o <<= 1) {
        int v = (t >= o) ? part[t - o] : 0;
        __syncthreads();
        part[t] += v;
        __syncthreads();
    }
    int run = (t == 0) ? 0 : part[t - 1];
    for (int i = beg; i < end; i++) {
        g_off[i] = run; g_cursor[i] = run; run += g_deg[i];
    }
    if (t == 255) g_off[NN] = part[255];
}

// ----------------------------------------------------------------------------
// L2: prep = transposes + hist; LAST block (done-counter) runs the scan.
// ----------------------------------------------------------------------------
#define PREP_BLOCKS (768 + HIST_BLOCKS)
__global__ void prep_kernel(const float* __restrict__ Wl1, const float* __restrict__ Wr1,
                            const float* __restrict__ Wl2, const float* __restrict__ Wr2,
                            const float* __restrict__ Wl3, const float* __restrict__ Wr3,
                            const int* __restrict__ edst) {
    int b = blockIdx.x, tid = threadIdx.x;
    if (b < 128) {
        int bz = b >> 6, i = b & 63;
        do_transpose(bz ? Wr1 : Wl1, g_wt1 + (size_t)bz * 512 * 128, 128, 512,
                     i & 15, i >> 4, tid);
    } else if (b < 640) {
        int i = b - 128;
        int bz = i >> 8; i &= 255;
        do_transpose(bz ? Wr2 : Wl2, g_wt2 + (size_t)bz * 512 * 512, 512, 512,
                     i & 15, i >> 4, tid);
    } else if (b < 768) {
        int i = b - 640;
        int bz = i >> 6; i &= 63;
        do_transpose(bz ? Wr3 : Wl3, g_wt3 + (size_t)bz * 128 * 512, 512, 128,
                     i & 3, i >> 2, tid);
    } else {
        int e = (b - 768) * 256 + tid;
        if (e < ET) {
            int d = (e < EE) ? edst[e] : (e - EE);
            atomicAdd(&g_deg[d], 1);
        }
    }
    // last-block-done scan
    __shared__ int s_last;
    __syncthreads();
    if (tid == 0) {
        __threadfence();
        unsigned int r = atomicAdd(&g_done, 1u);
        s_last = (r == PREP_BLOCKS - 1) ? 1 : 0;
    }
    __syncthreads();
    if (s_last) scan_256();
}

// ----------------------------------------------------------------------------
// fp16 mma.sync m16n8k16 GEMM body (4-stage cp.async, 128x128 block, 64x32 warp)
// ----------------------------------------------------------------------------
#define STAGES 4
#define SMEM_A_TILE (128 * 32)
#define SMEM_B_TILE (128 * 32)
#define SMEM_STAGE  (SMEM_A_TILE + SMEM_B_TILE)

__device__ __forceinline__ void gemm_body(
    __half* smh, const __half* __restrict__ A, const __half* __restrict__ BT,
    const float* __restrict__ bias_l, const float* __restrict__ bias_r,
    __half* __restrict__ C, int Nrows, int K, int Mout, int Mhalf,
    int bxi, int byi) {
    uint32_t uS = smem_u32(smh);

    int tid = threadIdx.x;
    int lane = tid & 31, wid = tid >> 5;
    int wm = wid & 1;
    int wn = wid >> 1;
    int g = lane >> 2, t = lane & 3;
    int brow = bxi * 128;
    int bcol = byi * 128;

    int cprow = tid >> 2;
    int cc = tid & 3;

    float acc[4][4][4];
#pragma unroll
    for (int a = 0; a < 4; a++)
#pragma unroll
        for (int b = 0; b < 4; b++)
#pragma unroll
            for (int c = 0; c < 4; c++) acc[a][b][c] = 0.f;

    const int NT = K >> 5;

    auto load_tile = [&](int kt, int buf) {
        int k0 = kt << 5;
        uint32_t base = uS + (uint32_t)(buf * SMEM_STAGE) * 2;
#pragma unroll
        for (int i = 0; i < 2; i++) {
            int row = cprow + i * 64;
            int gr = brow + row; if (gr >= Nrows) gr = Nrows - 1;
            cp_async16(base + (uint32_t)(row * 32 + cc * 8) * 2,
                       A + (size_t)gr * K + k0 + cc * 8);
        }
        base += (uint32_t)SMEM_A_TILE * 2;
#pragma unroll
        for (int i = 0; i < 2; i++) {
            int row = cprow + i * 64;
            cp_async16(base + (uint32_t)(row * 32 + cc * 8) * 2,
                       BT + (size_t)(bcol + row) * K + k0 + cc * 8);
        }
    };

#pragma unroll
    for (int p = 0; p < STAGES - 1; p++) {
        if (p < NT) load_tile(p, p);
        cp_commit();
    }

    for (int kt = 0; kt < NT; kt++) {
        cp_wait<STAGES - 2>();
        __syncthreads();
        int nk = kt + STAGES - 1;
        if (nk < NT) load_tile(nk, nk & (STAGES - 1));
        cp_commit();

        const __half* Ab = smh + (kt & (STAGES - 1)) * SMEM_STAGE;
        const __half* Bb = Ab + SMEM_A_TILE;

        uint4 bfv[4];
#pragma unroll
        for (int nt = 0; nt < 4; nt++) {
            int n = wn * 32 + nt * 8 + g;
            bfv[nt] = *(const uint4*)(Bb + n * 32 + t * 8);
        }
#pragma unroll
        for (int mt = 0; mt < 4; mt++) {
            int r = wm * 64 + mt * 16 + g;
            uint4 lo = *(const uint4*)(Ab + r * 32 + t * 8);
            uint4 hi = *(const uint4*)(Ab + (r + 8) * 32 + t * 8);
#pragma unroll
            for (int nt = 0; nt < 4; nt++) {
                asm volatile(
                    "mma.sync.aligned.m16n8k16.row.col.f32.f16.f16.f32 "
                    "{%0,%1,%2,%3}, {%4,%5,%6,%7}, {%8,%9}, {%0,%1,%2,%3};"
                    : "+f"(acc[mt][nt][0]), "+f"(acc[mt][nt][1]),
                      "+f"(acc[mt][nt][2]), "+f"(acc[mt][nt][3])
                    : "r"(lo.x), "r"(hi.x), "r"(lo.y), "r"(hi.y),
                      "r"(bfv[nt].x), "r"(bfv[nt].y));
                asm volatile(
                    "mma.sync.aligned.m16n8k16.row.col.f32.f16.f16.f32 "
                    "{%0,%1,%2,%3}, {%4,%5,%6,%7}, {%8,%9}, {%0,%1,%2,%3};"
                    : "+f"(acc[mt][nt][0]), "+f"(acc[mt][nt][1]),
                      "+f"(acc[mt][nt][2]), "+f"(acc[mt][nt][3])
                    : "r"(lo.z), "r"(hi.z), "r"(lo.w), "r"(hi.w),
                      "r"(bfv[nt].z), "r"(bfv[nt].w));
            }
        }
    }

#pragma unroll
    for (int mt = 0; mt < 4; mt++) {
        int r0 = brow + wm * 64 + mt * 16 + g;
#pragma unroll
        for (int nt = 0; nt < 4; nt++) {
            int c = bcol + wn * 32 + nt * 8 + 2 * t;
            float b0, b1;
            if (c < Mhalf) { b0 = bias_l[c]; b1 = bias_l[c + 1]; }
            else           { b0 = bias_r[c - Mhalf]; b1 = bias_r[c - Mhalf + 1]; }
            if (r0 < Nrows) {
                *(__half2*)(C + (size_t)r0 * Mout + c) =
                    __floats2half2_rn(acc[mt][nt][0] + b0, acc[mt][nt][1] + b1);
            }
            if (r0 + 8 < Nrows) {
                *(__half2*)(C + (size_t)(r0 + 8) * Mout + c) =
                    __floats2half2_rn(acc[mt][nt][2] + b0, acc[mt][nt][3] + b1);
            }
        }
    }
}

__global__ __launch_bounds__(256, 2)
void gemm_mma(const __half* __restrict__ A, const __half* __restrict__ BT,
              const float* __restrict__ bias_l, const float* __restrict__ bias_r,
              __half* __restrict__ C, int Nrows, int K, int Mout, int Mhalf) {
    extern __shared__ __half smh[];
    gemm_body(smh, A, BT, bias_l, bias_r, C, Nrows, K, Mout, Mhalf,
              blockIdx.x, blockIdx.y);
}

// L3: scatter (blocks 0..HIST_BLOCKS-1) + gemm1 (remaining RTC*8 blocks)
__global__ __launch_bounds__(256, 2)
void gemm1_scatter(const __half* __restrict__ A, const __half* __restrict__ BT,
                   const float* __restrict__ bias_l, const float* __restrict__ bias_r,
                   __half* __restrict__ C,
                   const int* __restrict__ esrc, const int* __restrict__ edst) {
    extern __shared__ __half smh[];
    int b = blockIdx.x;
    if (b < HIST_BLOCKS) {
        int e = b * 256 + threadIdx.x;
        if (e >= ET) return;
        int s, d;
        if (e < EE) { s = esrc[e]; d = edst[e]; }
        else        { s = e - EE;  d = e - EE; }
        int pos = atomicAdd(&g_cursor[d], 1);
        g_csr_src[pos] = s;
        return;
    }
    int gb = b - HIST_BLOCKS;
    gemm_body(smh, A, BT, bias_l, bias_r, C, NN, 128, 1024, 512,
              gb % RTC, gb / RTC);
}

// ----------------------------------------------------------------------------
// Fused GATv2 attention (online softmax), 4-edge ILP, one warp per (node, head)
// ----------------------------------------------------------------------------
template <int H, bool PERM>
__global__ __launch_bounds__(256)
void gatv2_fused(const __half* __restrict__ xlr,
                 const float* __restrict__ att, const float* __restrict__ bias,
                 void* __restrict__ outp) {
    const int S = 2 * H * 128;
    const int D = H * 128;
    int wg = blockIdx.x * 8 + (threadIdx.x >> 5);
    int node = wg / H;
    int h = wg % H;
    if (node >= NN) return;
    int lane = threadIdx.x & 31;
    int cbase = h * 128 + lane * 4;

    float4 rv = ldh4(xlr + (size_t)node * S + D + cbase);
    float4 av = *(const float4*)(att + cbase);
    int s = g_off[node], e = g_off[node + 1];

    float m = -1e30f, den = 0.f;
    float4 acc = make_float4(0.f, 0.f, 0.f, 0.f);

    int j = s;
    for (; j + 4 <= e; j += 4) {
        int s0 = g_csr_src[j],     s1 = g_csr_src[j + 1];
        int s2 = g_csr_src[j + 2], s3 = g_csr_src[j + 3];
        float4 x0 = ldh4(xlr + (size_t)s0 * S + cbase);
        float4 x1 = ldh4(xlr + (size_t)s1 * S + cbase);
        float4 x2 = ldh4(xlr + (size_t)s2 * S + cbase);
        float4 x3 = ldh4(xlr + (size_t)s3 * S + cbase);
        float p0 = 0.f, p1 = 0.f, p2 = 0.f, p3 = 0.f, tt;
        tt = x0.x + rv.x; tt = tt > 0.f ? tt : SLOPE * tt; p0 += av.x * tt;
        tt = x1.x + rv.x; tt = tt > 0.f ? tt : SLOPE * tt; p1 += av.x * tt;
        tt = x2.x + rv.x; tt = tt > 0.f ? tt : SLOPE * tt; p2 += av.x * tt;
        tt = x3.x + rv.x; tt = tt > 0.f ? tt : SLOPE * tt; p3 += av.x * tt;
        tt = x0.y + rv.y; tt = tt > 0.f ? tt : SLOPE * tt; p0 += av.y * tt;
        tt = x1.y + rv.y; tt = tt > 0.f ? tt : SLOPE * tt; p1 += av.y * tt;
        tt = x2.y + rv.y; tt = tt > 0.f ? tt : SLOPE * tt; p2 += av.y * tt;
        tt = x3.y + rv.y; tt = tt > 0.f ? tt : SLOPE * tt; p3 += av.y * tt;
        tt = x0.z + rv.z; tt = tt > 0.f ? tt : SLOPE * tt; p0 += av.z * tt;
        tt = x1.z + rv.z; tt = tt > 0.f ? tt : SLOPE * tt; p1 += av.z * tt;
        tt = x2.z + rv.z; tt = tt > 0.f ? tt : SLOPE * tt; p2 += av.z * tt;
        tt = x3.z + rv.z; tt = tt > 0.f ? tt : SLOPE * tt; p3 += av.z * tt;
        tt = x0.w + rv.w; tt = tt > 0.f ? tt : SLOPE * tt; p0 += av.w * tt;
        tt = x1.w + rv.w; tt = tt > 0.f ? tt : SLOPE * tt; p1 += av.w * tt;
        tt = x2.w + rv.w; tt = tt > 0.f ? tt : SLOPE * tt; p2 += av.w * tt;
        tt = x3.w + rv.w; tt = tt > 0.f ? tt : SLOPE * tt; p3 += av.w * tt;
#pragma unroll
        for (int o = 16; o; o >>= 1) {
            p0 += __shfl_xor_sync(0xffffffffu, p0, o);
            p1 += __shfl_xor_sync(0xffffffffu, p1, o);
            p2 += __shfl_xor_sync(0xffffffffu, p2, o);
            p3 += __shfl_xor_sync(0xffffffffu, p3, o);
        }
        float mm = fmaxf(fmaxf(m, fmaxf(p0, p1)), fmaxf(p2, p3));
        if (mm > m) {
            float sc = __expf(m - mm);
            m = mm;
            den *= sc; acc.x *= sc; acc.y *= sc; acc.z *= sc; acc.w *= sc;
        }
        float w0 = __expf(p0 - m), w1 = __expf(p1 - m);
        float w2 = __expf(p2 - m), w3 = __expf(p3 - m);
        den += (w0 + w1) + (w2 + w3);
        acc.x += w0 * x0.x + w1 * x1.x + w2 * x2.x + w3 * x3.x;
        acc.y += w0 * x0.y + w1 * x1.y + w2 * x2.y + w3 * x3.y;
        acc.z += w0 * x0.z + w1 * x1.z + w2 * x2.z + w3 * x3.z;
        acc.w += w0 * x0.w + w1 * x1.w + w2 * x2.w + w3 * x3.w;
    }
    for (; j < e; j++) {
        int s0 = g_csr_src[j];
        float4 x0 = ldh4(xlr + (size_t)s0 * S + cbase);
        float tt, p0 = 0.f;
        tt = x0.x + rv.x; tt = tt > 0.f ? tt : SLOPE * tt; p0 += av.x * tt;
        tt = x0.y + rv.y; tt = tt > 0.f ? tt : SLOPE * tt; p0 += av.y * tt;
        tt = x0.z + rv.z; tt = tt > 0.f ? tt : SLOPE * tt; p0 += av.z * tt;
        tt = x0.w + rv.w; tt = tt > 0.f ? tt : SLOPE * tt; p0 += av.w * tt;
#pragma unroll
        for (int o = 16; o; o >>= 1) p0 += __shfl_xor_sync(0xffffffffu, p0, o);
        if (p0 > m) {
            float sc = __expf(m - p0);
            m = p0;
            den *= sc; acc.x *= sc; acc.y *= sc; acc.z *= sc; acc.w *= sc;
        }
        float w0 = __expf(p0 - m);
        den += w0;
        acc.x += w0 * x0.x; acc.y += w0 * x0.y; acc.z += w0 * x0.z; acc.w += w0 * x0.w;
    }

    float inv = 1.f / den;
    float4 o4;
    float v;
    v = acc.x * inv + bias[cbase + 0]; o4.x = v > 0.f ? v : expm1f(v);
    v = acc.y * inv + bias[cbase + 1]; o4.y = v > 0.f ? v : expm1f(v);
    v = acc.z * inv + bias[cbase + 2]; o4.z = v > 0.f ? v : expm1f(v);
    v = acc.w * inv + bias[cbase + 3]; o4.w = v > 0.f ? v : expm1f(v);

    if (PERM) {
        __half* out = (__half*)outp;
        int lw = lane & 7;
        int q0 = pairperm(2 * lw);
        size_t base = (size_t)node * D + h * 128 + (lane >> 3) * 32 + 2 * q0;
        *(__half2*)(out + base)     = __floats2half2_rn(o4.x, o4.y);
        *(__half2*)(out + base + 8) = __floats2half2_rn(o4.z, o4.w);
    } else {
        float* out = (float*)outp;
        *(float4*)(out + (size_t)node * D + cbase) = o4;
    }
}

// ----------------------------------------------------------------------------
// Fused pool+MLP: block g pools its (contiguous) node segment, then runs MLP.
// ----------------------------------------------------------------------------
__global__ void pool_mlp_kernel(const int* __restrict__ batch,
                                const float* __restrict__ W1, const float* __restrict__ b1,
                                const float* __restrict__ W2, const float* __restrict__ b2,
                                float* __restrict__ out) {
    int g = blockIdx.x;
    int t = threadIdx.x;
    __shared__ int seg[2];
    __shared__ float p[HID];
    __shared__ float hid[HID];
    __shared__ float red[HID];
    if (t < 2) {
        int target = g + t;
        int lo = 0, hi = NN;
        while (lo < hi) {
            int mid = (lo + hi) >> 1;
            if (batch[mid] < target) lo = mid + 1; else hi = mid;
        }
        seg[t] = lo;
    }
    __syncthreads();
    int lo = seg[0], hi = seg[1];
    float sum = 0.f;
    for (int i = lo; i < hi; i++) sum += g_h3[(size_t)i * HID + t];
    float c = fmaxf((float)(hi - lo), 1.0f);
    p[t] = sum / c;
    __syncthreads();
    float a = 0.f;
    for (int k = 0; k < HID; k++) a += p[k] * W1[k * HID + t];
    hid[t] = fmaxf(a + b1[t], 0.f);
    __syncthreads();
    for (int o = 0; o < 2; o++) {
        red[t] = hid[t] * W2[t * 2 + o];
        __syncthreads();
        for (int stp = 64; stp; stp >>= 1) {
            if (t < stp) red[t] += red[t + stp];
            __syncthreads();
        }
        if (t == 0) out[g * 2 + o] = red[0] + b2[o];
        __syncthreads();
    }
}

// ----------------------------------------------------------------------------
// Launch
// ----------------------------------------------------------------------------
extern "C" void kernel_launch(void* const* d_in, const int* in_sizes, int n_in,
                              void* d_out, int out_size) {
    const float* x     = (const float*)d_in[0];
    const int*   esrc  = (const int*)d_in[1];
    const int*   edst  = (const int*)d_in[2];
    const int*   batch = (const int*)d_in[3];
    const float* Wl1 = (const float*)d_in[4];
    const float* Wr1 = (const float*)d_in[5];
    const float* bl1 = (const float*)d_in[6];
    const float* br1 = (const float*)d_in[7];
    const float* att1  = (const float*)d_in[8];
    const float* bias1 = (const float*)d_in[9];
    const float* Wl2 = (const float*)d_in[10];
    const float* Wr2 = (const float*)d_in[11];
    const float* bl2 = (const float*)d_in[12];
    const float* br2 = (const float*)d_in[13];
    const float* att2  = (const float*)d_in[14];
    const float* bias2 = (const float*)d_in[15];
    const float* Wl3 = (const float*)d_in[16];
    const float* Wr3 = (const float*)d_in[17];
    const float* bl3 = (const float*)d_in[18];
    const float* br3 = (const float*)d_in[19];
    const float* att3  = (const float*)d_in[20];
    const float* bias3 = (const float*)d_in[21];
    const float* Wm1 = (const float*)d_in[22];
    const float* bm1 = (const float*)d_in[23];
    const float* Wm2 = (const float*)d_in[24];
    const float* bm2 = (const float*)d_in[25];
    float* out = (float*)d_out;

    float *p_h3;
    __half *p_xlr, *p_h1, *p_h2, *p_xp, *p_wt1, *p_wt2, *p_wt3;
    cudaGetSymbolAddress((void**)&p_xlr, g_xlr);
    cudaGetSymbolAddress((void**)&p_h1, g_h1);
    cudaGetSymbolAddress((void**)&p_h2, g_h2);
    cudaGetSymbolAddress((void**)&p_h3, g_h3);
    cudaGetSymbolAddress((void**)&p_xp, g_xp);
    cudaGetSymbolAddress((void**)&p_wt1, g_wt1);
    cudaGetSymbolAddress((void**)&p_wt2, g_wt2);
    cudaGetSymbolAddress((void**)&p_wt3, g_wt3);

    const int SMEM = STAGES * SMEM_STAGE * 2;  // 65536 bytes
    cudaFuncSetAttribute(gemm_mma, cudaFuncAttributeMaxDynamicSharedMemorySize, SMEM);
    cudaFuncSetAttribute(gemm1_scatter, cudaFuncAttributeMaxDynamicSharedMemorySize, SMEM);

    const int AB = (NN * HEADS + 7) / 8;

    // L1: permute + zero
    permute_zero_kernel<<<10000 + (NN + 255) / 256, 256>>>(x, p_xp);
    // L2: transposes + hist + (last block) scan
    prep_kernel<<<PREP_BLOCKS, 256>>>(Wl1, Wr1, Wl2, Wr2, Wl3, Wr3, edst);
    // L3: scatter + gemm1
    gemm1_scatter<<<HIST_BLOCKS + RTC * 8, 256, SMEM>>>(p_xp, p_wt1, bl1, br1,
                                                        p_xlr, esrc, edst);
    // L4: attention 1  (profiled slot)
    gatv2_fused<HEADS, true><<<AB, 256>>>(p_xlr, att1, bias1, p_h1);
    // L5: gemm2
    gemm_mma<<<dim3(RTC, 8), 256, SMEM>>>(p_h1, p_wt2, bl2, br2, p_xlr, NN, 512, 1024, 512);
    // L6: attention 2
    gatv2_fused<HEADS, true><<<AB, 256>>>(p_xlr, att2, bias2, p_h2);
    // L7: gemm3
    gemm_mma<<<dim3(RTC, 2), 256, SMEM>>>(p_h2, p_wt3, bl3, br3, p_xlr, NN, 512, 256, 128);
    // L8: attention 3
    gatv2_fused<1, false><<<(NN + 7) / 8, 256>>>(p_xlr, att3, bias3, p_h3);
    // L9: pool + MLP fused
    pool_mlp_kernel<<<BGR, HID>>>(batch, Wm1, bm1, Wm2, bm2, out);
}